// round 13
// baseline (speedup 1.0000x reference)
#include <cuda_runtime.h>
#include <math.h>

// Problem constants
#define BATCH 32
#define CH    512
#define HWSZ  4096          // 64*64
#define HID   64
#define FAN1  768

// Scratch (no allocs allowed in kernel_launch). Counters self-reset -> graph safe.
__device__ float g_xc [BATCH * CH];   // spatial means
__device__ float g_a  [BATCH * CH];   // attention scalars
__device__ int   g_cnt[BATCH];        // per-batch completion counters

// ---------------------------------------------------------------------------
// Kernel 1: mean + (last-block) attention.
// One block per (b,c) row; 256 threads x 4 float4 coalesced loads (the access
// pattern measured at 82% DRAM / 6.6 TB/s). The 512th-finishing block of each
// batch computes that batch's attention scalars inline via the rank-1
// factorization of the reference math:
//   y[q]  = mean(xc[4q..4q+3])                       (q < 128)
//   A[h]  = dot(xc, W1[h,0:512]) + b1[h]
//   Bc[h] = sum_q y[q] * (W1[h,512+q] + W1[h,640+q])
//   a[c]  = sigmoid( sum_h w2[h]*relu(A[h] + xc[c]*Bc[h]) + b2 )
// Default-cached reads leave the tail of x in L2 for the scale pass.
// ---------------------------------------------------------------------------
__global__ __launch_bounds__(256) void mean_attn_kernel(
    const float* __restrict__ x,
    const float* __restrict__ w1,   // [64, 768]
    const float* __restrict__ b1,   // [64]
    const float* __restrict__ w2,   // [1, 64]
    const float* __restrict__ b2)   // [1]
{
    const int bc  = blockIdx.x;
    const int b   = bc >> 9;
    const int tid = threadIdx.x;

    const float4* __restrict__ xp =
        reinterpret_cast<const float4*>(x) + (size_t)bc * (HWSZ / 4);

    float4 v0 = xp[tid];
    float4 v1 = xp[tid + 256];
    float4 v2 = xp[tid + 512];
    float4 v3 = xp[tid + 768];

    float s = ((v0.x + v0.y) + (v0.z + v0.w))
            + ((v1.x + v1.y) + (v1.z + v1.w))
            + ((v2.x + v2.y) + (v2.z + v2.w))
            + ((v3.x + v3.y) + (v3.z + v3.w));

#pragma unroll
    for (int o = 16; o; o >>= 1) s += __shfl_down_sync(0xffffffffu, s, o);

    __shared__ float ws[8];
    __shared__ int   is_last;
    const int lane = tid & 31, wrp = tid >> 5;
    if (lane == 0) ws[wrp] = s;
    __syncthreads();
    if (tid == 0) {
        float t = 0.0f;
#pragma unroll
        for (int i = 0; i < 8; i++) t += ws[i];
        g_xc[bc] = t * (1.0f / HWSZ);
        __threadfence();                        // publish mean before counting
        int old = atomicAdd(&g_cnt[b], 1);
        is_last = (old == CH - 1);
    }
    __syncthreads();
    if (!is_last) return;

    // ============ last block of batch b: compute a[b, 0..511] ==============
    __threadfence();   // acquire: all 512 means of batch b visible

    __shared__ float xc[CH];
    __shared__ float yv[128];
    __shared__ float Aarr[HID];
    __shared__ float Barr[HID];
    __shared__ float w2s[HID];

    xc[tid]       = __ldcg(&g_xc[b * CH + tid]);
    xc[tid + 256] = __ldcg(&g_xc[b * CH + tid + 256]);
    if (tid < HID) w2s[tid] = w2[tid];
    __syncthreads();

    if (tid < 128) {
        yv[tid] = 0.25f * (xc[4 * tid] + xc[4 * tid + 1] +
                           xc[4 * tid + 2] + xc[4 * tid + 3]);
    }
    __syncthreads();

    {   // 4 threads cooperate per hidden unit h (coalesced W1 row reads)
        const int h = tid >> 2;
        const int l = tid & 3;
        const float* __restrict__ wr = w1 + h * FAN1;
        float A = 0.0f, Bv = 0.0f;
#pragma unroll 8
        for (int j = l; j < CH; j += 4) A = fmaf(xc[j], wr[j], A);
#pragma unroll 8
        for (int q = l; q < 128; q += 4)
            Bv = fmaf(yv[q], wr[512 + q] + wr[640 + q], Bv);

        A  += __shfl_xor_sync(0xffffffffu, A, 1);
        A  += __shfl_xor_sync(0xffffffffu, A, 2);
        Bv += __shfl_xor_sync(0xffffffffu, Bv, 1);
        Bv += __shfl_xor_sync(0xffffffffu, Bv, 2);
        if (l == 0) { Aarr[h] = A + b1[h]; Barr[h] = Bv; }
    }
    __syncthreads();

    const float bias2 = b2[0];
#pragma unroll
    for (int cc = 0; cc < 2; cc++) {
        const int   c  = tid + cc * 256;
        const float xv = xc[c];
        float acc = bias2;
#pragma unroll
        for (int h = 0; h < HID; h++) {
            float sv = fmaf(xv, Barr[h], Aarr[h]);
            acc = fmaf(w2s[h], fmaxf(sv, 0.0f), acc);
        }
        g_a[b * CH + c] = 1.0f / (1.0f + expf(-acc));
    }

    if (tid == 0) g_cnt[b] = 0;   // self-reset for graph replay
}

// ---------------------------------------------------------------------------
// Kernel 2: out = x * a[b,c]. One block per (b,c) row in REVERSE order (the
// mean pass left the tail of x resident in L2 — consume it first at L2
// bandwidth). 'a' is block-uniform. Same 4x-float4 MLP pattern as the mean
// kernel. __ldcs = evict-first on x (no further reuse); __stcs on out keeps
// store-allocate from displacing unconsumed x lines.
// ---------------------------------------------------------------------------
__global__ __launch_bounds__(256) void scale_kernel(
    const float4* __restrict__ x, float4* __restrict__ out)
{
    const int row = (int)gridDim.x - 1 - (int)blockIdx.x;
    const float a = __ldg(&g_a[row]);

    const float4* __restrict__ xp = x   + (size_t)row * (HWSZ / 4);
    float4*       __restrict__ op = out + (size_t)row * (HWSZ / 4);
    const int t = threadIdx.x;

    float4 v0 = __ldcs(xp + t);
    float4 v1 = __ldcs(xp + t + 256);
    float4 v2 = __ldcs(xp + t + 512);
    float4 v3 = __ldcs(xp + t + 768);

    v0.x *= a; v0.y *= a; v0.z *= a; v0.w *= a;
    v1.x *= a; v1.y *= a; v1.z *= a; v1.w *= a;
    v2.x *= a; v2.y *= a; v2.z *= a; v2.w *= a;
    v3.x *= a; v3.y *= a; v3.z *= a; v3.w *= a;

    __stcs(op + t,       v0);
    __stcs(op + t + 256, v1);
    __stcs(op + t + 512, v2);
    __stcs(op + t + 768, v3);
}

// ---------------------------------------------------------------------------
extern "C" void kernel_launch(void* const* d_in, const int* in_sizes, int n_in,
                              void* d_out, int out_size) {
    const float* x     = (const float*)d_in[0];  // [32,512,64,64]
    const float* fc1_w = (const float*)d_in[1];  // [64,768]
    const float* fc1_b = (const float*)d_in[2];  // [64]
    const float* fc2_w = (const float*)d_in[3];  // [1,64]
    const float* fc2_b = (const float*)d_in[4];  // [1]
    float* out = (float*)d_out;

    mean_attn_kernel<<<BATCH * CH, 256>>>(x, fc1_w, fc1_b, fc2_w, fc2_b);
    scale_kernel<<<BATCH * CH, 256>>>(
        reinterpret_cast<const float4*>(x), reinterpret_cast<float4*>(out));
}

// round 14
// speedup vs baseline: 2.0610x; 2.0610x over previous
#include <cuda_runtime.h>
#include <math.h>

// Problem constants
#define BATCH 32
#define CH    512
#define HWSZ  4096          // 64*64
#define HID   64
#define FAN1  768

// Scratch (no allocs allowed in kernel_launch)
__device__ float g_xc[BATCH * CH];   // spatial means
__device__ float g_a [BATCH * CH];   // attention scalars

// ---------------------------------------------------------------------------
// Kernel 1: x_c[b,c] = mean over 4096 spatial elems. One block per (b,c) row.
// 256 threads x 4 batched float4 loads (measured 82% DRAM / 6.6 TB/s).
// NO fences/atomics — gpu-scope __threadfence emits CCTL.IVALL (full L1D
// invalidate) and cost ~160us when fused (R13 post-mortem).
// Default-cached reads leave the tail of x in L2 for the scale pass.
// ---------------------------------------------------------------------------
__global__ __launch_bounds__(256) void mean_pool_kernel(const float* __restrict__ x) {
    const int bc  = blockIdx.x;
    const int tid = threadIdx.x;
    const float4* __restrict__ xp =
        reinterpret_cast<const float4*>(x) + (size_t)bc * (HWSZ / 4);

    float4 v0 = xp[tid];
    float4 v1 = xp[tid + 256];
    float4 v2 = xp[tid + 512];
    float4 v3 = xp[tid + 768];

    float s = ((v0.x + v0.y) + (v0.z + v0.w))
            + ((v1.x + v1.y) + (v1.z + v1.w))
            + ((v2.x + v2.y) + (v2.z + v2.w))
            + ((v3.x + v3.y) + (v3.z + v3.w));

#pragma unroll
    for (int o = 16; o; o >>= 1) s += __shfl_down_sync(0xffffffffu, s, o);

    __shared__ float ws[8];
    const int lane = tid & 31, w = tid >> 5;
    if (lane == 0) ws[w] = s;
    __syncthreads();
    if (tid == 0) {
        float t = 0.0f;
#pragma unroll
        for (int i = 0; i < 8; i++) t += ws[i];
        g_xc[bc] = t * (1.0f / HWSZ);
    }
}

// ---------------------------------------------------------------------------
// Kernel 2: per-batch attention scalars (rank-1 factorization of reference):
//   y[q]  = mean(xc[4q..4q+3])                       (q < 128)
//   A[h]  = dot(xc, W1[h,0:512]) + b1[h]
//   Bc[h] = sum_q y[q] * (W1[h,512+q] + W1[h,640+q])
//   a[c]  = sigmoid( sum_h w2[h]*relu(A[h] + xc[c]*Bc[h]) + b2 )
// One block per batch, 256 threads. ~2us total.
// ---------------------------------------------------------------------------
__global__ __launch_bounds__(256) void attention_kernel(
    const float* __restrict__ w1,   // [64, 768]
    const float* __restrict__ b1,   // [64]
    const float* __restrict__ w2,   // [1, 64]
    const float* __restrict__ b2)   // [1]
{
    __shared__ float xc[CH];
    __shared__ float yv[128];
    __shared__ float Aarr[HID];
    __shared__ float Barr[HID];
    __shared__ float w2s[HID];

    const int b   = blockIdx.x;
    const int tid = threadIdx.x;

    xc[tid]       = g_xc[b * CH + tid];
    xc[tid + 256] = g_xc[b * CH + tid + 256];
    if (tid < HID) w2s[tid] = w2[tid];
    __syncthreads();

    if (tid < 128) {
        yv[tid] = 0.25f * (xc[4 * tid] + xc[4 * tid + 1] +
                           xc[4 * tid + 2] + xc[4 * tid + 3]);
    }
    __syncthreads();

    {   // 4 threads cooperate per hidden unit h (coalesced W1 row reads)
        const int h = tid >> 2;
        const int l = tid & 3;
        const float* __restrict__ wr = w1 + h * FAN1;
        float A = 0.0f, Bv = 0.0f;
#pragma unroll 8
        for (int j = l; j < CH; j += 4) A = fmaf(xc[j], wr[j], A);
#pragma unroll 8
        for (int q = l; q < 128; q += 4)
            Bv = fmaf(yv[q], wr[512 + q] + wr[640 + q], Bv);

        A  += __shfl_xor_sync(0xffffffffu, A, 1);
        A  += __shfl_xor_sync(0xffffffffu, A, 2);
        Bv += __shfl_xor_sync(0xffffffffu, Bv, 1);
        Bv += __shfl_xor_sync(0xffffffffu, Bv, 2);
        if (l == 0) { Aarr[h] = A + b1[h]; Barr[h] = Bv; }
    }
    __syncthreads();

    const float bias2 = b2[0];
#pragma unroll
    for (int cc = 0; cc < 2; cc++) {
        const int   c  = tid + cc * 256;
        const float xv = xc[c];
        float acc = bias2;
#pragma unroll
        for (int h = 0; h < HID; h++) {
            float sv = fmaf(xv, Barr[h], Aarr[h]);
            acc = fmaf(w2s[h], fmaxf(sv, 0.0f), acc);
        }
        g_a[b * CH + c] = 1.0f / (1.0f + expf(-acc));
    }
}

// ---------------------------------------------------------------------------
// Kernel 3: out = x * a[b,c]. EXACTLY the R13 version measured at 73.9us /
// 82% DRAM. One block per (b,c) row in REVERSE order (consume the x tail the
// mean pass left in L2 first). 'a' is block-uniform. __ldcs on x (evict-first,
// no reuse), __stcs on out (don't displace unconsumed x lines).
// ---------------------------------------------------------------------------
__global__ __launch_bounds__(256) void scale_kernel(
    const float4* __restrict__ x, float4* __restrict__ out)
{
    const int row = (int)gridDim.x - 1 - (int)blockIdx.x;
    const float a = __ldg(&g_a[row]);

    const float4* __restrict__ xp = x   + (size_t)row * (HWSZ / 4);
    float4*       __restrict__ op = out + (size_t)row * (HWSZ / 4);
    const int t = threadIdx.x;

    float4 v0 = __ldcs(xp + t);
    float4 v1 = __ldcs(xp + t + 256);
    float4 v2 = __ldcs(xp + t + 512);
    float4 v3 = __ldcs(xp + t + 768);

    v0.x *= a; v0.y *= a; v0.z *= a; v0.w *= a;
    v1.x *= a; v1.y *= a; v1.z *= a; v1.w *= a;
    v2.x *= a; v2.y *= a; v2.z *= a; v2.w *= a;
    v3.x *= a; v3.y *= a; v3.z *= a; v3.w *= a;

    __stcs(op + t,       v0);
    __stcs(op + t + 256, v1);
    __stcs(op + t + 512, v2);
    __stcs(op + t + 768, v3);
}

// ---------------------------------------------------------------------------
extern "C" void kernel_launch(void* const* d_in, const int* in_sizes, int n_in,
                              void* d_out, int out_size) {
    const float* x     = (const float*)d_in[0];  // [32,512,64,64]
    const float* fc1_w = (const float*)d_in[1];  // [64,768]
    const float* fc1_b = (const float*)d_in[2];  // [64]
    const float* fc2_w = (const float*)d_in[3];  // [1,64]
    const float* fc2_b = (const float*)d_in[4];  // [1]
    float* out = (float*)d_out;

    mean_pool_kernel<<<BATCH * CH, 256>>>(x);
    attention_kernel<<<BATCH, 256>>>(fc1_w, fc1_b, fc2_w, fc2_b);
    scale_kernel<<<BATCH * CH, 256>>>(
        reinterpret_cast<const float4*>(x), reinterpret_cast<float4*>(out));
}

// round 16
// speedup vs baseline: 2.0720x; 1.0053x over previous
#include <cuda_runtime.h>
#include <math.h>

// Problem constants
#define BATCH 32
#define CH    512
#define HWSZ  4096          // 64*64
#define HID   64
#define FAN1  768

// Scratch (no allocs allowed in kernel_launch)
__device__ float g_xc[BATCH * CH];   // spatial means
__device__ float g_a [BATCH * CH];   // attention scalars

// ---------------------------------------------------------------------------
// Kernel 1: x_c[b,c] = mean over 4096 spatial elems. One block per (b,c) row.
// 256 threads x 4 batched float4 loads (measured 82% DRAM / 6.6 TB/s).
// PDL trigger at the END (after the g_xc store is in flight): writes before
// the trigger are the ones guaranteed visible to the secondary after its
// cudaGridDependencySynchronize (R15 failed by triggering before the store).
// ---------------------------------------------------------------------------
__global__ __launch_bounds__(256) void mean_pool_kernel(const float* __restrict__ x) {
    const int bc  = blockIdx.x;
    const int tid = threadIdx.x;
    const float4* __restrict__ xp =
        reinterpret_cast<const float4*>(x) + (size_t)bc * (HWSZ / 4);

    float4 v0 = xp[tid];
    float4 v1 = xp[tid + 256];
    float4 v2 = xp[tid + 512];
    float4 v3 = xp[tid + 768];

    float s = ((v0.x + v0.y) + (v0.z + v0.w))
            + ((v1.x + v1.y) + (v1.z + v1.w))
            + ((v2.x + v2.y) + (v2.z + v2.w))
            + ((v3.x + v3.y) + (v3.z + v3.w));

#pragma unroll
    for (int o = 16; o; o >>= 1) s += __shfl_down_sync(0xffffffffu, s, o);

    __shared__ float ws[8];
    const int lane = tid & 31, w = tid >> 5;
    if (lane == 0) ws[w] = s;
    __syncthreads();
    if (tid == 0) {
        float t = 0.0f;
#pragma unroll
        for (int i = 0; i < 8; i++) t += ws[i];
        g_xc[bc] = t * (1.0f / HWSZ);
    }
    __syncthreads();                         // g_xc store precedes all triggers
    cudaTriggerProgrammaticLaunchCompletion();
}

// ---------------------------------------------------------------------------
// Kernel 2: per-batch attention scalars (rank-1 factorization of reference):
//   y[q]  = mean(xc[4q..4q+3])                       (q < 128)
//   A[h]  = dot(xc, W1[h,0:512]) + b1[h]
//   Bc[h] = sum_q y[q] * (W1[h,512+q] + W1[h,640+q])
//   a[c]  = sigmoid( sum_h w2[h]*relu(A[h] + xc[c]*Bc[h]) + b2 )
// One block per batch, 256 threads. PDL secondary of mean: prefetches the
// mean-independent weights before the sync; triggers only AFTER g_a stores.
// ---------------------------------------------------------------------------
__global__ __launch_bounds__(256) void attention_kernel(
    const float* __restrict__ w1,   // [64, 768]
    const float* __restrict__ b1,   // [64]
    const float* __restrict__ w2,   // [1, 64]
    const float* __restrict__ b2)   // [1]
{
    __shared__ float xc[CH];
    __shared__ float yv[128];
    __shared__ float Aarr[HID];
    __shared__ float Barr[HID];
    __shared__ float w2s[HID];

    const int b   = blockIdx.x;
    const int tid = threadIdx.x;

    // Weight loads are independent of the means — issue before the sync.
    if (tid < HID) w2s[tid] = w2[tid];

    cudaGridDependencySynchronize();   // wait: mean kernel's g_xc visible

    xc[tid]       = g_xc[b * CH + tid];
    xc[tid + 256] = g_xc[b * CH + tid + 256];
    __syncthreads();

    if (tid < 128) {
        yv[tid] = 0.25f * (xc[4 * tid] + xc[4 * tid + 1] +
                           xc[4 * tid + 2] + xc[4 * tid + 3]);
    }
    __syncthreads();

    {   // 4 threads cooperate per hidden unit h (coalesced W1 row reads)
        const int h = tid >> 2;
        const int l = tid & 3;
        const float* __restrict__ wr = w1 + h * FAN1;
        float A = 0.0f, Bv = 0.0f;
#pragma unroll 8
        for (int j = l; j < CH; j += 4) A = fmaf(xc[j], wr[j], A);
#pragma unroll 8
        for (int q = l; q < 128; q += 4)
            Bv = fmaf(yv[q], wr[512 + q] + wr[640 + q], Bv);

        A  += __shfl_xor_sync(0xffffffffu, A, 1);
        A  += __shfl_xor_sync(0xffffffffu, A, 2);
        Bv += __shfl_xor_sync(0xffffffffu, Bv, 1);
        Bv += __shfl_xor_sync(0xffffffffu, Bv, 2);
        if (l == 0) { Aarr[h] = A + b1[h]; Barr[h] = Bv; }
    }
    __syncthreads();

    const float bias2 = b2[0];
#pragma unroll
    for (int cc = 0; cc < 2; cc++) {
        const int   c  = tid + cc * 256;
        const float xv = xc[c];
        float acc = bias2;
#pragma unroll
        for (int h = 0; h < HID; h++) {
            float sv = fmaf(xv, Barr[h], Aarr[h]);
            acc = fmaf(w2s[h], fmaxf(sv, 0.0f), acc);
        }
        g_a[b * CH + c] = 1.0f / (1.0f + expf(-acc));
    }
    __syncthreads();                         // g_a stores precede all triggers
    cudaTriggerProgrammaticLaunchCompletion();
}

// ---------------------------------------------------------------------------
// Kernel 3: out = x * a[b,c]. PDL secondary of attention. The x-row loads are
// input-only and dependency-free, so they issue BEFORE the sync (overlapping
// attention's drain). Then sync, read a, scale, store. Reverse block order +
// __ldcs/__stcs preserved (measured 73.9us / 82% DRAM).
// ---------------------------------------------------------------------------
__global__ __launch_bounds__(256) void scale_kernel(
    const float4* __restrict__ x, float4* __restrict__ out)
{
    const int row = (int)gridDim.x - 1 - (int)blockIdx.x;
    const float4* __restrict__ xp = x   + (size_t)row * (HWSZ / 4);
    float4*       __restrict__ op = out + (size_t)row * (HWSZ / 4);
    const int t = threadIdx.x;

    float4 v0 = __ldcs(xp + t);
    float4 v1 = __ldcs(xp + t + 256);
    float4 v2 = __ldcs(xp + t + 512);
    float4 v3 = __ldcs(xp + t + 768);

    cudaGridDependencySynchronize();   // wait: attention's g_a visible

    const float a = __ldg(&g_a[row]);

    v0.x *= a; v0.y *= a; v0.z *= a; v0.w *= a;
    v1.x *= a; v1.y *= a; v1.z *= a; v1.w *= a;
    v2.x *= a; v2.y *= a; v2.z *= a; v2.w *= a;
    v3.x *= a; v3.y *= a; v3.z *= a; v3.w *= a;

    __stcs(op + t,       v0);
    __stcs(op + t + 256, v1);
    __stcs(op + t + 512, v2);
    __stcs(op + t + 768, v3);
}

// ---------------------------------------------------------------------------
extern "C" void kernel_launch(void* const* d_in, const int* in_sizes, int n_in,
                              void* d_out, int out_size) {
    const float* x     = (const float*)d_in[0];  // [32,512,64,64]
    const float* fc1_w = (const float*)d_in[1];  // [64,768]
    const float* fc1_b = (const float*)d_in[2];  // [64]
    const float* fc2_w = (const float*)d_in[3];  // [1,64]
    const float* fc2_b = (const float*)d_in[4];  // [1]
    float* out = (float*)d_out;

    // PDL attribute for secondary launches
    cudaLaunchAttribute pdl_attr;
    pdl_attr.id = cudaLaunchAttributeProgrammaticStreamSerialization;
    pdl_attr.val.programmaticStreamSerializationAllowed = 1;

    // K1: mean (normal launch; triggers PDL completion after g_xc stores)
    mean_pool_kernel<<<BATCH * CH, 256>>>(x);

    // K2: attention (PDL secondary of mean)
    {
        cudaLaunchConfig_t cfg = {};
        cfg.gridDim  = dim3(BATCH, 1, 1);
        cfg.blockDim = dim3(256, 1, 1);
        cfg.stream   = 0;
        cfg.attrs    = &pdl_attr;
        cfg.numAttrs = 1;
        cudaLaunchKernelEx(&cfg, attention_kernel, fc1_w, fc1_b, fc2_w, fc2_b);
    }

    // K3: scale (PDL secondary of attention; prefetches x before the sync)
    {
        cudaLaunchConfig_t cfg = {};
        cfg.gridDim  = dim3(BATCH * CH, 1, 1);
        cfg.blockDim = dim3(256, 1, 1);
        cfg.stream   = 0;
        cfg.attrs    = &pdl_attr;
        cfg.numAttrs = 1;
        cudaLaunchKernelEx(&cfg, scale_kernel,
                           reinterpret_cast<const float4*>(x),
                           reinterpret_cast<float4*>(out));
    }
}